// round 1
// baseline (speedup 1.0000x reference)
#include <cuda_runtime.h>
#include <math.h>

#define H      128
#define H3     384
#define BATCH  64
#define TT     2048
#define TILE   128   // time steps staged per smem chunk

// feat[b*256 + dir*128 + i] = mean over t of hidden state
__device__ float g_feat[BATCH * 2 * H];

__device__ __forceinline__ float sigmoidf_(float x) {
    return 1.0f / (1.0f + expf(-x));
}

// One persistent block per (batch, direction). 384 threads; thread j owns
// output column j of the 3H pre-activations with Wh[:,j] in registers.
__global__ void __launch_bounds__(H3, 1) gru_persist_kernel(
    const float* __restrict__ y, const float* __restrict__ u,
    const float* __restrict__ Wi_f, const float* __restrict__ bi_f,
    const float* __restrict__ Wh_f, const float* __restrict__ bhn_f,
    const float* __restrict__ Wi_b, const float* __restrict__ bi_b,
    const float* __restrict__ Wh_b, const float* __restrict__ bhn_b)
{
    const int blk = blockIdx.x;        // 0..127
    const int b   = blk & (BATCH - 1); // batch index
    const int dir = blk >> 6;          // 0 = fwd, 1 = bwd
    const int j   = threadIdx.x;       // 0..383

    const float* Wi  = dir ? Wi_b  : Wi_f;
    const float* bi  = dir ? bi_b  : bi_f;
    const float* Wh  = dir ? Wh_b  : Wh_f;
    const float* bhn = dir ? bhn_b : bhn_f;

    // ---- register-resident weights ----
    float w[H];                 // Wh[k][j], k = 0..127
#pragma unroll
    for (int k = 0; k < H; ++k) w[k] = Wh[k * H3 + j];

    float wi[8];                // Wi[d][j], d = 0..7
#pragma unroll
    for (int d = 0; d < 8; ++d) wi[d] = Wi[d * H3 + j];

    const float bij   = bi[j];
    const float bhn_i = (j < H) ? bhn[j] : 0.0f;

    // ---- shared state ----
    __shared__ float4 h4[H / 4];        // hidden state, 128 floats
    __shared__ float  r_s[H], z_s[H], xwn_s[H], hpn_s[H];
    __shared__ float4 yu_s[TILE * 2];   // per step: y(4) + u(4) = 2 float4

    if (j < H / 4) h4[j] = make_float4(0.f, 0.f, 0.f, 0.f);
    __syncthreads();

    float hsum = 0.0f;                  // per-hidden-unit running sum (j < H)

    const int nchunk = TT / TILE;
    for (int c = 0; c < nchunk; ++c) {
        const int t0 = dir ? (TT - (c + 1) * TILE) : (c * TILE);

        // stage this chunk's inputs (threads 0..127, one step each)
        if (j < TILE) {
            const int t = t0 + j;
            yu_s[2 * j]     = *(const float4*)(y + ((size_t)b * TT + t) * 4);
            yu_s[2 * j + 1] = *(const float4*)(u + ((size_t)b * TT + t) * 4);
        }
        __syncthreads();

        for (int s = 0; s < TILE; ++s) {
            const int tt = dir ? (TILE - 1 - s) : s;

            // ---- phase 1: pre-activations ----
            const float4 ya = yu_s[2 * tt];
            const float4 ub = yu_s[2 * tt + 1];
            float xw = bij;
            xw += ya.x * wi[0]; xw += ya.y * wi[1];
            xw += ya.z * wi[2]; xw += ya.w * wi[3];
            xw += ub.x * wi[4]; xw += ub.y * wi[5];
            xw += ub.z * wi[6]; xw += ub.w * wi[7];

            float d0 = 0.f, d1 = 0.f, d2 = 0.f, d3 = 0.f;
#pragma unroll
            for (int kk = 0; kk < H / 4; ++kk) {
                const float4 hv = h4[kk];   // broadcast, conflict-free
                d0 += hv.x * w[4 * kk + 0];
                d1 += hv.y * w[4 * kk + 1];
                d2 += hv.z * w[4 * kk + 2];
                d3 += hv.w * w[4 * kk + 3];
            }
            const float dot = (d0 + d1) + (d2 + d3);

            if (j < H) {
                r_s[j] = sigmoidf_(xw + dot);
            } else if (j < 2 * H) {
                z_s[j - H] = sigmoidf_(xw + dot);
            } else {
                xwn_s[j - 2 * H] = xw;
                hpn_s[j - 2 * H] = dot;
            }
            __syncthreads();

            // ---- phase 2: gate combine + state update (threads 0..127) ----
            if (j < H) {
                const float hold = ((const float*)h4)[j];
                const float n  = tanhf(xwn_s[j] + r_s[j] * (hpn_s[j] + bhn_i));
                const float z  = z_s[j];
                const float hn = n + z * (hold - n);   // (1-z)*n + z*h
                hsum += hn;
                ((float*)h4)[j] = hn;
            }
            __syncthreads();
        }
    }

    if (j < H)
        g_feat[b * (2 * H) + dir * H + j] = hsum * (1.0f / (float)TT);
}

// MLP heads: sizes 256 -> 128 -> 64 -> 20, tanh, tanh, linear. Two heads.
// One block per batch row; weights streamed from gmem (L2-shared across blocks).
__global__ void __launch_bounds__(128) mlp_kernel(
    const float* __restrict__ mW0, const float* __restrict__ mb0,
    const float* __restrict__ mW1, const float* __restrict__ mb1,
    const float* __restrict__ mW2, const float* __restrict__ mb2,
    const float* __restrict__ sW0, const float* __restrict__ sb0,
    const float* __restrict__ sW1, const float* __restrict__ sb1,
    const float* __restrict__ sW2, const float* __restrict__ sb2,
    float* __restrict__ out)
{
    const int b = blockIdx.x;
    const int j = threadIdx.x;

    __shared__ float feat_s[256];
    __shared__ float h1_s[128];
    __shared__ float h2_s[64];

    feat_s[j]       = g_feat[b * 256 + j];
    feat_s[j + 128] = g_feat[b * 256 + j + 128];
    __syncthreads();

    for (int head = 0; head < 2; ++head) {
        const float* W0 = head ? sW0 : mW0;
        const float* b0 = head ? sb0 : mb0;
        const float* W1 = head ? sW1 : mW1;
        const float* b1 = head ? sb1 : mb1;
        const float* W2 = head ? sW2 : mW2;
        const float* b2 = head ? sb2 : mb2;

        // layer 0: 256 -> 128
        {
            float acc = b0[j];
#pragma unroll 8
            for (int i = 0; i < 256; ++i) acc += feat_s[i] * W0[i * 128 + j];
            h1_s[j] = tanhf(acc);
        }
        __syncthreads();

        // layer 1: 128 -> 64
        if (j < 64) {
            float acc = b1[j];
#pragma unroll 8
            for (int i = 0; i < 128; ++i) acc += h1_s[i] * W1[i * 64 + j];
            h2_s[j] = tanhf(acc);
        }
        __syncthreads();

        // layer 2: 64 -> 20
        if (j < 20) {
            float acc = b2[j];
#pragma unroll
            for (int i = 0; i < 64; ++i) acc += h2_s[i] * W2[i * 20 + j];
            out[head * (BATCH * 20) + b * 20 + j] = acc;
        }
        __syncthreads();
    }
}

extern "C" void kernel_launch(void* const* d_in, const int* in_sizes, int n_in,
                              void* d_out, int out_size)
{
    const float* y     = (const float*)d_in[0];
    const float* u     = (const float*)d_in[1];
    const float* Wi_f  = (const float*)d_in[2];
    const float* bi_f  = (const float*)d_in[3];
    const float* Wh_f  = (const float*)d_in[4];
    const float* bhn_f = (const float*)d_in[5];
    const float* Wi_b  = (const float*)d_in[6];
    const float* bi_b  = (const float*)d_in[7];
    const float* Wh_b  = (const float*)d_in[8];
    const float* bhn_b = (const float*)d_in[9];
    const float* mW0   = (const float*)d_in[10];
    const float* mb0   = (const float*)d_in[11];
    const float* mW1   = (const float*)d_in[12];
    const float* mb1   = (const float*)d_in[13];
    const float* mW2   = (const float*)d_in[14];
    const float* mb2   = (const float*)d_in[15];
    const float* sW0   = (const float*)d_in[16];
    const float* sb0   = (const float*)d_in[17];
    const float* sW1   = (const float*)d_in[18];
    const float* sb1   = (const float*)d_in[19];
    const float* sW2   = (const float*)d_in[20];
    const float* sb2   = (const float*)d_in[21];

    gru_persist_kernel<<<BATCH * 2, H3>>>(y, u, Wi_f, bi_f, Wh_f, bhn_f,
                                          Wi_b, bi_b, Wh_b, bhn_b);
    mlp_kernel<<<BATCH, 128>>>(mW0, mb0, mW1, mb1, mW2, mb2,
                               sW0, sb0, sW1, sb1, sW2, sb2,
                               (float*)d_out);
}

// round 2
// speedup vs baseline: 1.8348x; 1.8348x over previous
#include <cuda_runtime.h>
#include <math.h>

#define H      128
#define H3     384
#define BATCH  64
#define TT     2048
#define TILE   128   // time steps staged per smem chunk

typedef unsigned long long ull_t;

// feat[b*256 + dir*128 + i] = mean over t of hidden state
__device__ float g_feat[BATCH * 2 * H];

__device__ __forceinline__ ull_t pack2(float lo, float hi) {
    return (ull_t)__float_as_uint(lo) | ((ull_t)__float_as_uint(hi) << 32);
}
__device__ __forceinline__ float lo2(ull_t v) { return __uint_as_float((unsigned)v); }
__device__ __forceinline__ float hi2(ull_t v) { return __uint_as_float((unsigned)(v >> 32)); }

__device__ __forceinline__ ull_t ffma2(ull_t a, ull_t b, ull_t c) {
    ull_t d;
    asm("fma.rn.f32x2 %0, %1, %2, %3;" : "=l"(d) : "l"(a), "l"(b), "l"(c));
    return d;
}
__device__ __forceinline__ ull_t fadd2(ull_t a, ull_t b) {
    ull_t d;
    asm("add.rn.f32x2 %0, %1, %2;" : "=l"(d) : "l"(a), "l"(b));
    return d;
}

// fast sigmoid / tanh via MUFU-based __expf; rel err ~1e-6 (budget 1e-3)
__device__ __forceinline__ float fsig(float x) {
    return __fdividef(1.0f, 1.0f + __expf(-x));
}
__device__ __forceinline__ float ftanh(float x) {
    return __fdividef(2.0f, 1.0f + __expf(-2.0f * x)) - 1.0f;
}

// One persistent block per (batch, direction). 384 threads; thread j owns
// column j of the 3H pre-activations with Wh[:,j] packed f32x2 in registers.
// j <  128: r-gate column j
// j <  256: z-gate column j-128
// j >= 256: n-gate column j-256, also performs the h update.
__global__ void __launch_bounds__(H3, 1) gru_persist_kernel(
    const float* __restrict__ y, const float* __restrict__ u,
    const float* __restrict__ Wi_f, const float* __restrict__ bi_f,
    const float* __restrict__ Wh_f, const float* __restrict__ bhn_f,
    const float* __restrict__ Wi_b, const float* __restrict__ bi_b,
    const float* __restrict__ Wh_b, const float* __restrict__ bhn_b)
{
    const int blk = blockIdx.x;        // 0..127
    const int b   = blk & (BATCH - 1); // batch index
    const int dir = blk >> 6;          // 0 = fwd, 1 = bwd
    const int j   = threadIdx.x;       // 0..383

    const float* Wi  = dir ? Wi_b  : Wi_f;
    const float* bi  = dir ? bi_b  : bi_f;
    const float* Wh  = dir ? Wh_b  : Wh_f;
    const float* bhn = dir ? bhn_b : bhn_f;

    // ---- register-resident weights, packed pairs along k ----
    ull_t w2[H / 2];
#pragma unroll
    for (int kk = 0; kk < H / 2; ++kk) {
        const float wlo = Wh[(2 * kk)     * H3 + j];
        const float whi = Wh[(2 * kk + 1) * H3 + j];
        w2[kk] = pack2(wlo, whi);
    }

    float wi[8];
#pragma unroll
    for (int d = 0; d < 8; ++d) wi[d] = Wi[d * H3 + j];

    const float bij   = bi[j];
    const float bhn_i = (j >= 2 * H) ? bhn[j - 2 * H] : 0.0f;

    // ---- shared state ----
    __shared__ __align__(16) float h_s[H];   // hidden state
    __shared__ float r_s[H], z_s[H];
    __shared__ float4 yu_s[TILE * 2];        // per step: y(4) + u(4)

    if (j < H) h_s[j] = 0.0f;
    __syncthreads();

    float hsum = 0.0f;                       // running sum (n-threads only)

    const int nchunk = TT / TILE;
    for (int c = 0; c < nchunk; ++c) {
        const int t0 = dir ? (TT - (c + 1) * TILE) : (c * TILE);

        // stage this chunk's inputs (threads 0..127, one step each)
        if (j < TILE) {
            const int t = t0 + j;
            yu_s[2 * j]     = *(const float4*)(y + ((size_t)b * TT + t) * 4);
            yu_s[2 * j + 1] = *(const float4*)(u + ((size_t)b * TT + t) * 4);
        }
        __syncthreads();

        for (int s = 0; s < TILE; ++s) {
            const int tt = dir ? (TILE - 1 - s) : s;

            // ---- phase 1: pre-activations ----
            const float4 ya = yu_s[2 * tt];
            const float4 ub = yu_s[2 * tt + 1];
            float xw = bij;
            xw = fmaf(ya.x, wi[0], xw); xw = fmaf(ya.y, wi[1], xw);
            xw = fmaf(ya.z, wi[2], xw); xw = fmaf(ya.w, wi[3], xw);
            xw = fmaf(ub.x, wi[4], xw); xw = fmaf(ub.y, wi[5], xw);
            xw = fmaf(ub.z, wi[6], xw); xw = fmaf(ub.w, wi[7], xw);

            // packed dot product: h[0:128] . w2  (LDS.128 -> 2 packed ops)
            const ulonglong2* h2 = (const ulonglong2*)h_s;
            ull_t a0 = 0ull, a1 = 0ull;      // (0.0f, 0.0f) packed
#pragma unroll
            for (int m = 0; m < H / 4; ++m) {
                const ulonglong2 hv = h2[m];  // broadcast, conflict-free
                a0 = ffma2(hv.x, w2[2 * m],     a0);
                a1 = ffma2(hv.y, w2[2 * m + 1], a1);
            }
            const ull_t asum = fadd2(a0, a1);
            const float dot = lo2(asum) + hi2(asum);

            if (j < H) {
                r_s[j] = fsig(xw + dot);
            } else if (j < 2 * H) {
                z_s[j - H] = fsig(xw + dot);
            }
            __syncthreads();

            // ---- phase 2: n-gate threads do the state update ----
            if (j >= 2 * H) {
                const int i = j - 2 * H;
                const float hold = h_s[i];
                const float n  = ftanh(xw + r_s[i] * (dot + bhn_i));
                const float hn = n + z_s[i] * (hold - n);   // (1-z)*n + z*h
                hsum += hn;
                h_s[i] = hn;
            }
            __syncthreads();
        }
    }

    if (j >= 2 * H)
        g_feat[b * (2 * H) + dir * H + (j - 2 * H)] = hsum * (1.0f / (float)TT);
}

// MLP heads: sizes 256 -> 128 -> 64 -> 20, tanh, tanh, linear.
// One block per (batch, head); weights streamed from gmem (L2-shared).
__global__ void __launch_bounds__(128) mlp_kernel(
    const float* __restrict__ mW0, const float* __restrict__ mb0,
    const float* __restrict__ mW1, const float* __restrict__ mb1,
    const float* __restrict__ mW2, const float* __restrict__ mb2,
    const float* __restrict__ sW0, const float* __restrict__ sb0,
    const float* __restrict__ sW1, const float* __restrict__ sb1,
    const float* __restrict__ sW2, const float* __restrict__ sb2,
    float* __restrict__ out)
{
    const int b    = blockIdx.x & (BATCH - 1);
    const int head = blockIdx.x >> 6;
    const int j    = threadIdx.x;

    const float* W0 = head ? sW0 : mW0;
    const float* b0 = head ? sb0 : mb0;
    const float* W1 = head ? sW1 : mW1;
    const float* b1 = head ? sb1 : mb1;
    const float* W2 = head ? sW2 : mW2;
    const float* b2 = head ? sb2 : mb2;

    __shared__ float feat_s[256];
    __shared__ float h1_s[128];
    __shared__ float h2_s[64];

    feat_s[j]       = g_feat[b * 256 + j];
    feat_s[j + 128] = g_feat[b * 256 + j + 128];
    __syncthreads();

    // layer 0: 256 -> 128
    {
        float acc = b0[j];
#pragma unroll 8
        for (int i = 0; i < 256; ++i) acc = fmaf(feat_s[i], W0[i * 128 + j], acc);
        h1_s[j] = tanhf(acc);
    }
    __syncthreads();

    // layer 1: 128 -> 64
    if (j < 64) {
        float acc = b1[j];
#pragma unroll 8
        for (int i = 0; i < 128; ++i) acc = fmaf(h1_s[i], W1[i * 64 + j], acc);
        h2_s[j] = tanhf(acc);
    }
    __syncthreads();

    // layer 2: 64 -> 20
    if (j < 20) {
        float acc = b2[j];
#pragma unroll
        for (int i = 0; i < 64; ++i) acc = fmaf(h2_s[i], W2[i * 20 + j], acc);
        out[head * (BATCH * 20) + b * 20 + j] = acc;
    }
}

extern "C" void kernel_launch(void* const* d_in, const int* in_sizes, int n_in,
                              void* d_out, int out_size)
{
    const float* y     = (const float*)d_in[0];
    const float* u     = (const float*)d_in[1];
    const float* Wi_f  = (const float*)d_in[2];
    const float* bi_f  = (const float*)d_in[3];
    const float* Wh_f  = (const float*)d_in[4];
    const float* bhn_f = (const float*)d_in[5];
    const float* Wi_b  = (const float*)d_in[6];
    const float* bi_b  = (const float*)d_in[7];
    const float* Wh_b  = (const float*)d_in[8];
    const float* bhn_b = (const float*)d_in[9];
    const float* mW0   = (const float*)d_in[10];
    const float* mb0   = (const float*)d_in[11];
    const float* mW1   = (const float*)d_in[12];
    const float* mb1   = (const float*)d_in[13];
    const float* mW2   = (const float*)d_in[14];
    const float* mb2   = (const float*)d_in[15];
    const float* sW0   = (const float*)d_in[16];
    const float* sb0   = (const float*)d_in[17];
    const float* sW1   = (const float*)d_in[18];
    const float* sb1   = (const float*)d_in[19];
    const float* sW2   = (const float*)d_in[20];
    const float* sb2   = (const float*)d_in[21];

    gru_persist_kernel<<<BATCH * 2, H3>>>(y, u, Wi_f, bi_f, Wh_f, bhn_f,
                                          Wi_b, bi_b, Wh_b, bhn_b);
    mlp_kernel<<<BATCH * 2, 128>>>(mW0, mb0, mW1, mb1, mW2, mb2,
                                   sW0, sb0, sW1, sb1, sW2, sb2,
                                   (float*)d_out);
}